// round 12
// baseline (speedup 1.0000x reference)
#include <cuda_runtime.h>
#include <cuda_bf16.h>
#include <cstdint>

#define NROWS 8192
#define DIM   128
#define CHUNK 128                  // samples per tile
#define NBLOCKS 256                // b<128: X; idx=b&127 -> chunk=idx>>1, nhalf=idx&1
#define NTHREADS 512               // 16 warps
#define FIN_BLOCKS 16

// ---------------- device-global scratch (no allocations allowed) -----------
// Zero at load; finalize restores the zeroed state every launch.
// g_G[m][r] holds replica r of P_m = H^T H + 2 H^T L  (contention split).
__device__ float    g_G[2][2][DIM * DIM];
__device__ float    g_S1;               // <Px,Py>_F partial accumulator
__device__ float    g_S2;               // sum d_i^2
__device__ float    g_S3;               // sum d_i
__device__ unsigned g_ticket;

// ---------------- helpers ---------------------------------------------------
__device__ __forceinline__ uint32_t smem_u32(const void* p) {
    uint32_t a;
    asm("{ .reg .u64 t; cvta.to.shared.u64 t, %1; cvt.u32.u64 %0, t; }" : "=r"(a) : "l"(p));
    return a;
}

// Tile stored SAMPLE-major: S[k][d]; two 16KB subtiles by d>>6; SW128 swizzle.
__device__ __forceinline__ uint32_t toff(int k, int d) {
    uint32_t o = (uint32_t)(k * 128 + (d & 63) * 2);
    o ^= (o >> 3) & 0x70;
    return (uint32_t)((d >> 6) * 16384) + o;
}

#define LO_OFF     32768           // 2*lo tile after hi tile (each 32KB)
#define SMEM_TOTAL 65536

__device__ __forceinline__ void ldsm4t(uint32_t* r, uint32_t addr) {
    asm volatile("ldmatrix.sync.aligned.m8n8.x4.trans.shared.b16 {%0,%1,%2,%3}, [%4];"
                 : "=r"(r[0]), "=r"(r[1]), "=r"(r[2]), "=r"(r[3]) : "r"(addr));
}

__device__ __forceinline__ void mma_bf16(float* d, const uint32_t* a,
                                         uint32_t b0, uint32_t b1) {
    asm volatile(
        "mma.sync.aligned.m16n8k16.row.col.f32.bf16.bf16.f32 "
        "{%0,%1,%2,%3}, {%4,%5,%6,%7}, {%8,%9}, {%0,%1,%2,%3};"
        : "+f"(d[0]), "+f"(d[1]), "+f"(d[2]), "+f"(d[3])
        : "r"(a[0]), "r"(a[1]), "r"(a[2]), "r"(a[3]), "r"(b0), "r"(b1));
}

// Non-returning vector atomic add (sm_90+).
__device__ __forceinline__ void red_add_v2(float* p, float a, float b) {
    asm volatile("red.global.add.v2.f32 [%0], {%1, %2};"
                 :: "l"(p), "f"(a), "f"(b) : "memory");
}

// ---------------------------------------------------------------------------
// Kernel 1: convert(+diag) -> tensor-core P = H^T H + H^T(2L) -> red.v2 merge.
// 256 blocks: block handles (chunk, column-half); 2 CTAs/SM co-resident.
// Warp w owns rows [(w&7)*16,+16) x cols [nhalf*64 + (w>>3)*32, +32).
// ---------------------------------------------------------------------------
__global__ __launch_bounds__(NTHREADS, 2)
void gram_diag(const float* __restrict__ X, const float* __restrict__ Y) {
    extern __shared__ char smem[];
    const uint32_t sb = smem_u32(smem);
    const int tid  = threadIdx.x;
    const int w    = tid >> 5;
    const int lane = tid & 31;

    const bool isX   = blockIdx.x < (NBLOCKS / 2);
    const int  idx   = blockIdx.x & (NBLOCKS / 2 - 1);
    const int  chunk = idx >> 1;
    const int  nhalf = idx & 1;
    const float* base  = (isX ? X : Y) + (size_t)chunk * CHUNK * DIM;
    const float* ybase = Y + (size_t)chunk * CHUNK * DIM;   // diag (X blocks)

    // ldmatrix per-lane tile-row selectors
    const int lr    = lane & 7;
    const int a_kad = (lane & 16) ? 8 : 0;
    const int a_mad = (lane & 8)  ? 8 : 0;
    const int b_kad = (lane & 8)  ? 8 : 0;
    const int b_nad = (lane & 16) ? 8 : 0;
    const int m0    = (w & 7) * 16;                 // warp's output row slab
    const int nbase = nhalf * 64 + (w >> 3) * 32;   // warp's output col range

    // ---- convert fp32 -> bf16 hi and 2*lo tiles; diag on (X, nhalf=0) ----
    float s2 = 0.0f, s3 = 0.0f;
    #pragma unroll
    for (int it = 0; it < 8; ++it) {
        const int r = w + 16 * it;                    // sample row
        const float4 v = *reinterpret_cast<const float4*>(base + r * DIM + lane * 4);
        __nv_bfloat162 h01 = __floats2bfloat162_rn(v.x, v.y);
        __nv_bfloat162 h23 = __floats2bfloat162_rn(v.z, v.w);
        __nv_bfloat162 l01 = __floats2bfloat162_rn(2.0f * (v.x - __bfloat162float(h01.x)),
                                                   2.0f * (v.y - __bfloat162float(h01.y)));
        __nv_bfloat162 l23 = __floats2bfloat162_rn(2.0f * (v.z - __bfloat162float(h23.x)),
                                                   2.0f * (v.w - __bfloat162float(h23.y)));
        const uint32_t o = toff(r, lane * 4);
        uint2 hv, lv;
        hv.x = *reinterpret_cast<uint32_t*>(&h01);
        hv.y = *reinterpret_cast<uint32_t*>(&h23);
        lv.x = *reinterpret_cast<uint32_t*>(&l01);
        lv.y = *reinterpret_cast<uint32_t*>(&l23);
        *reinterpret_cast<uint2*>(smem + o)          = hv;
        *reinterpret_cast<uint2*>(smem + LO_OFF + o) = lv;

        if (isX && nhalf == 0) {                      // diag: d_r = <x_r, y_r>
            const float4 u = *reinterpret_cast<const float4*>(ybase + r * DIM + lane * 4);
            float d = v.x * u.x + v.y * u.y + v.z * u.z + v.w * u.w;
            #pragma unroll
            for (int o2 = 16; o2; o2 >>= 1) d += __shfl_xor_sync(0xffffffffu, d, o2);
            s3 += d;
            s2 += d * d;
        }
    }
    if (isX && nhalf == 0 && lane == 0) {
        atomicAdd(&g_S3, s3);
        atomicAdd(&g_S2, s2);
    }
    __syncthreads();

    // ---- MMA mainloop: acc[nt][i], nt = 0..3 (8-col tiles in 32-col range) --
    float acc[4][4];
    #pragma unroll
    for (int nt = 0; nt < 4; ++nt)
        #pragma unroll
        for (int i = 0; i < 4; ++i) acc[nt][i] = 0.0f;

    for (int ks = 0; ks < 8; ++ks) {
        const int k0 = ks * 16;
        uint32_t ahi[4];
        ldsm4t(ahi, sb + toff(k0 + lr + a_kad, m0 + a_mad));

        #pragma unroll
        for (int ntp = 0; ntp < 2; ++ntp) {
            const int n0 = nbase + ntp * 16;
            uint32_t bhi[4], blo[4];
            const uint32_t boff = toff(k0 + lr + b_kad, n0 + b_nad);
            ldsm4t(bhi, sb + boff);
            ldsm4t(blo, sb + LO_OFF + boff);
            mma_bf16(acc[2 * ntp],     ahi, bhi[0], bhi[1]);
            mma_bf16(acc[2 * ntp],     ahi, blo[0], blo[1]);
            mma_bf16(acc[2 * ntp + 1], ahi, bhi[2], bhi[3]);
            mma_bf16(acc[2 * ntp + 1], ahi, blo[2], blo[3]);
        }
    }

    // ---- merge partial P with v2 vector atomics (replica by chunk parity) --
    float* G = g_G[isX ? 0 : 1][chunk & 1];
    const int row0 = m0 + (lane >> 2);
    const int col0 = (lane & 3) * 2;
    #pragma unroll
    for (int nt = 0; nt < 4; ++nt) {
        const int cc = nbase + nt * 8 + col0;
        red_add_v2(&G[row0 * DIM + cc],       acc[nt][0], acc[nt][1]);
        red_add_v2(&G[(row0 + 8) * DIM + cc], acc[nt][2], acc[nt][3]);
    }
}

// ---------------------------------------------------------------------------
// Kernel 2: 16 blocks x 256. Each block dots+zeros its own slice of both
// replicas, float-atomics the partial into g_S1; ticket-last combines+resets.
// ---------------------------------------------------------------------------
__global__ __launch_bounds__(256, 1)
void finalize(float* __restrict__ out) {
    __shared__ float    wsum[8];
    __shared__ unsigned s_last;
    const int tid  = threadIdx.x;
    const int lane = tid & 31;
    const int w    = tid >> 5;
    const int i    = blockIdx.x * 256 + tid;   // float4 index (4096 per array)

    const float4* X0 = reinterpret_cast<const float4*>(g_G[0][0]);
    const float4* X1 = reinterpret_cast<const float4*>(g_G[0][1]);
    const float4* Y0 = reinterpret_cast<const float4*>(g_G[1][0]);
    const float4* Y1 = reinterpret_cast<const float4*>(g_G[1][1]);
    const float4 a0 = X0[i], a1 = X1[i], b0 = Y0[i], b1 = Y1[i];
    const float ax = a0.x + a1.x, ay = a0.y + a1.y, az = a0.z + a1.z, aw = a0.w + a1.w;
    const float bx = b0.x + b1.x, by = b0.y + b1.y, bz = b0.z + b1.z, bw = b0.w + b1.w;
    float s1 = ax * bx + ay * by + az * bz + aw * bw;

    // zero own slices (only this block touches these addresses)
    const float4 z = make_float4(0.f, 0.f, 0.f, 0.f);
    reinterpret_cast<float4*>(g_G[0][0])[i] = z;
    reinterpret_cast<float4*>(g_G[0][1])[i] = z;
    reinterpret_cast<float4*>(g_G[1][0])[i] = z;
    reinterpret_cast<float4*>(g_G[1][1])[i] = z;

    #pragma unroll
    for (int o = 16; o; o >>= 1) s1 += __shfl_xor_sync(0xffffffffu, s1, o);
    if (lane == 0) wsum[w] = s1;
    __syncthreads();

    if (tid == 0) {
        float t = 0.0f;
        #pragma unroll
        for (int k = 0; k < 8; ++k) t += wsum[k];
        atomicAdd(&g_S1, t);
        __threadfence();
        s_last = atomicAdd(&g_ticket, 1u);
        if (s_last == FIN_BLOCKS - 1) {
            const float S1 = atomicAdd(&g_S1, 0.0f);   // coherent read
            const double loss =
                ((double)S1 - (double)g_S2) / ((double)NROWS * (double)(NROWS - 1))
                - 2.0 * (double)g_S3 / (double)NROWS;
            out[0] = (float)loss;
            g_S1 = 0.0f; g_S2 = 0.0f; g_S3 = 0.0f; g_ticket = 0u;
        }
    }
}

// ---------------------------------------------------------------------------
extern "C" void kernel_launch(void* const* d_in, const int* in_sizes, int n_in,
                              void* d_out, int out_size) {
    const float* X = (const float*)d_in[0];
    const float* Y = (const float*)d_in[1];
    float* out = (float*)d_out;

    static bool attr_set = false;   // idempotent host-side attribute
    if (!attr_set) {
        cudaFuncSetAttribute(gram_diag,
                             cudaFuncAttributeMaxDynamicSharedMemorySize, SMEM_TOTAL);
        attr_set = true;
    }

    gram_diag<<<NBLOCKS, NTHREADS, SMEM_TOTAL>>>(X, Y);
    finalize<<<FIN_BLOCKS, 256>>>(out);
}